// round 5
// baseline (speedup 1.0000x reference)
#include <cuda_runtime.h>
#include <cuda_fp16.h>
#include <cstdint>

#define N_NODES 50000
#define N_EDGES 1600000
#define G_GRAPHS 256
#define IN_CH 64
#define EC 32
#define H_CH 64
#define OUT_CH 10

// ---------------- scratch ----------------
__device__ float  g_edge_aggr[N_NODES * EC];
__device__ __half g_y[N_NODES * H_CH];        // fp16 gather payload
__device__ float  g_yp[N_NODES * 128];        // layer-0 partial (x @ W[0:64]) fp32
__device__ float  g_u[N_NODES * H_CH];
__device__ float  g_agg[N_NODES * H_CH];
__device__ float  g_x[N_NODES * H_CH];
__device__ float  g_pooled[G_GRAPHS * H_CH];
__device__ int    g_icnt[2 * N_NODES];
__device__ int    g_off[N_NODES + 1];
__device__ int    g_csr[N_EDGES];

// ---------------- PTX helpers ----------------
__device__ __forceinline__ void red4(float* addr, float4 v) {
    asm volatile("red.global.add.v4.f32 [%0], {%1,%2,%3,%4};"
                 :: "l"(addr), "f"(v.x), "f"(v.y), "f"(v.z), "f"(v.w)
                 : "memory");
}
__device__ __forceinline__ void ffma2(unsigned long long& d,
                                      unsigned long long a, unsigned long long b) {
    asm("fma.rn.f32x2 %0, %1, %2, %0;" : "+l"(d) : "l"(a), "l"(b));
}
__device__ __forceinline__ unsigned long long bcast2(float a) {
    unsigned long long r;
    asm("mov.b64 %0, {%1, %1};" : "=l"(r) : "f"(a));
    return r;
}
__device__ __forceinline__ float2 u2f(unsigned long long v) {
    float2 f;
    asm("mov.b64 {%0, %1}, %2;" : "=f"(f.x), "=f"(f.y) : "l"(v));
    return f;
}

// ---------------- CSR build ----------------
__global__ void k_hist(const int* __restrict__ edge_index) {
    int e = blockIdx.x * blockDim.x + threadIdx.x;
    if (e >= N_EDGES) return;
    atomicAdd(&g_icnt[edge_index[N_EDGES + e]], 1);
}

__global__ void k_scan() {
    __shared__ int wsum[32];
    __shared__ int chunk_base;
    int tid = threadIdx.x, lane = tid & 31, wid = tid >> 5;
    if (tid == 0) chunk_base = 0;
    for (int start = 0; start < N_NODES; start += 4096) {
        __syncthreads();
        int idx = start + tid * 4;
        int a0 = 0, a1 = 0, a2 = 0, a3 = 0;
        if (idx + 3 < N_NODES) {
            int4 t = *reinterpret_cast<const int4*>(&g_icnt[idx]);
            a0 = t.x; a1 = t.y; a2 = t.z; a3 = t.w;
        } else if (idx < N_NODES) {
            a0 = g_icnt[idx];
            if (idx + 1 < N_NODES) a1 = g_icnt[idx + 1];
            if (idx + 2 < N_NODES) a2 = g_icnt[idx + 2];
        }
        int v = a0 + a1 + a2 + a3;
        int x = v;
#pragma unroll
        for (int d = 1; d < 32; d <<= 1) {
            int y = __shfl_up_sync(0xffffffffu, x, d);
            if (lane >= d) x += y;
        }
        if (lane == 31) wsum[wid] = x;
        __syncthreads();
        if (wid == 0) {
            int s = wsum[lane];
#pragma unroll
            for (int d = 1; d < 32; d <<= 1) {
                int y = __shfl_up_sync(0xffffffffu, s, d);
                if (lane >= d) s += y;
            }
            wsum[lane] = s;
        }
        __syncthreads();
        int wbase = (wid > 0) ? wsum[wid - 1] : 0;
        int base = chunk_base + wbase + x - v;
        if (idx < N_NODES)     g_off[idx]     = base;
        if (idx + 1 < N_NODES) g_off[idx + 1] = base + a0;
        if (idx + 2 < N_NODES) g_off[idx + 2] = base + a0 + a1;
        if (idx + 3 < N_NODES) g_off[idx + 3] = base + a0 + a1 + a2;
        __syncthreads();
        if (tid == 0) chunk_base += wsum[31];
    }
    __syncthreads();
    if (tid == 0) g_off[N_NODES] = chunk_base;
}

__global__ void k_fill(const int* __restrict__ edge_index) {
    int e = blockIdx.x * blockDim.x + threadIdx.x;
    if (e >= N_EDGES) return;
    int c = edge_index[N_EDGES + e];
    int pos = g_off[c] + atomicAdd(&g_icnt[N_NODES + c], 1);
    g_csr[pos] = edge_index[e];
}

// ---------------- edge_attr aggregation ----------------
__global__ void k_edge_aggr(const float* __restrict__ edge_attr,
                            const int* __restrict__ edge_index,
                            float* __restrict__ out) {
    const int Q = N_EDGES / 4;
    int tid = blockIdx.x * blockDim.x + threadIdx.x;
    int e = tid >> 3, p4 = (tid & 7) * 4;
    if (e >= Q) return;
    int e1 = e + Q, e2 = e + 2 * Q, e3 = e + 3 * Q;
    int r0 = edge_index[e],  r1 = edge_index[e1];
    int r2 = edge_index[e2], r3 = edge_index[e3];
    float4 v0 = *reinterpret_cast<const float4*>(edge_attr + (size_t)e  * EC + p4);
    float4 v1 = *reinterpret_cast<const float4*>(edge_attr + (size_t)e1 * EC + p4);
    float4 v2 = *reinterpret_cast<const float4*>(edge_attr + (size_t)e2 * EC + p4);
    float4 v3 = *reinterpret_cast<const float4*>(edge_attr + (size_t)e3 * EC + p4);
    red4(out + (size_t)r0 * EC + p4, v0);
    red4(out + (size_t)r1 * EC + p4, v1);
    red4(out + (size_t)r2 * EC + p4, v2);
    red4(out + (size_t)r3 * EC + p4, v3);
}

// ---------------- CSR gather v3: warp per node, no intra-warp divergence ----------------
__global__ void k_gather() {
    int node = (blockIdx.x * blockDim.x + threadIdx.x) >> 5;
    if (node >= N_NODES) return;
    int lane = threadIdx.x & 31;
    int g = lane >> 3;            // edge subgroup 0..3
    int p8 = (lane & 7) * 8;      // 8 halves = 16B column chunk
    int s = g_off[node], e = g_off[node + 1];

    float a0[8], a1[8];
#pragma unroll
    for (int q = 0; q < 8; q++) { a0[q] = 0.f; a1[q] = 0.f; }

    int i = s + g;
    for (; i + 4 < e; i += 8) {
        int n0 = g_csr[i], n1 = g_csr[i + 4];
        uint4 v0 = *reinterpret_cast<const uint4*>(&g_y[(size_t)n0 * H_CH + p8]);
        uint4 v1 = *reinterpret_cast<const uint4*>(&g_y[(size_t)n1 * H_CH + p8]);
        const __half2* h0 = reinterpret_cast<const __half2*>(&v0);
        const __half2* h1 = reinterpret_cast<const __half2*>(&v1);
#pragma unroll
        for (int q = 0; q < 4; q++) {
            float2 f0 = __half22float2(h0[q]);
            float2 f1 = __half22float2(h1[q]);
            a0[q * 2]     += f0.x;  a0[q * 2 + 1] += f0.y;
            a1[q * 2]     += f1.x;  a1[q * 2 + 1] += f1.y;
        }
    }
    if (i < e) {
        int n0 = g_csr[i];
        uint4 v0 = *reinterpret_cast<const uint4*>(&g_y[(size_t)n0 * H_CH + p8]);
        const __half2* h0 = reinterpret_cast<const __half2*>(&v0);
#pragma unroll
        for (int q = 0; q < 4; q++) {
            float2 f0 = __half22float2(h0[q]);
            a0[q * 2]     += f0.x;  a0[q * 2 + 1] += f0.y;
        }
    }

    float r[8];
#pragma unroll
    for (int q = 0; q < 8; q++) {
        r[q] = a0[q] + a1[q];
        r[q] += __shfl_xor_sync(0xffffffffu, r[q], 8);
        r[q] += __shfl_xor_sync(0xffffffffu, r[q], 16);
    }
    if (g == 0) {
        float4 o0 = make_float4(r[0], r[1], r[2], r[3]);
        float4 o1 = make_float4(r[4], r[5], r[6], r[7]);
        *reinterpret_cast<float4*>(&g_agg[(size_t)node * H_CH + p8])     = o0;
        *reinterpret_cast<float4*>(&g_agg[(size_t)node * H_CH + p8 + 4]) = o1;
    }
}

// ---------------- layer-0 mlp1 part A: yp = x @ Wcat[0:64,:]  (overlaps edge_aggr) ----------------
__global__ void k_mlp1a(const float* __restrict__ x_in,
                        const float* __restrict__ W1_rel,
                        const float* __restrict__ W1_root) {
    extern __shared__ float sm[];
    float* xs = sm;            // [64][68]
    float* Ws = sm + 64 * 68;  // [64][128]
    const int tid = threadIdx.x;
    const int node0 = blockIdx.x * 64;

    for (int i = tid; i < 64 * 128; i += 256) {
        int k = i >> 7, j = i & 127;
        Ws[i] = (j < 64) ? W1_rel[k * 64 + j] : W1_root[k * 64 + (j - 64)];
    }
    for (int i = tid; i < 64 * 64; i += 256) {
        int n = i >> 6, k = i & 63;
        int node = node0 + n;
        xs[n * 68 + k] = (node < N_NODES) ? x_in[(size_t)node * 64 + k] : 0.f;
    }
    __syncthreads();

    const int og = tid & 15, ng = tid >> 4;
    const int j0 = og * 8;
    unsigned long long acc[4][4];
#pragma unroll
    for (int i = 0; i < 4; i++)
#pragma unroll
        for (int j = 0; j < 4; j++) acc[i][j] = 0ull;

#pragma unroll 4
    for (int k = 0; k < 64; k++) {
        ulonglong2 wA = *reinterpret_cast<const ulonglong2*>(&Ws[k * 128 + j0]);
        ulonglong2 wB = *reinterpret_cast<const ulonglong2*>(&Ws[k * 128 + j0 + 4]);
#pragma unroll
        for (int i = 0; i < 4; i++) {
            unsigned long long aa = bcast2(xs[(ng + 16 * i) * 68 + k]);
            ffma2(acc[i][0], aa, wA.x);
            ffma2(acc[i][1], aa, wA.y);
            ffma2(acc[i][2], aa, wB.x);
            ffma2(acc[i][3], aa, wB.y);
        }
    }

#pragma unroll
    for (int i = 0; i < 4; i++) {
        int node = node0 + ng + 16 * i;
        if (node >= N_NODES) continue;
        float2 f0 = u2f(acc[i][0]), f1 = u2f(acc[i][1]);
        float2 f2 = u2f(acc[i][2]), f3 = u2f(acc[i][3]);
        *reinterpret_cast<float4*>(&g_yp[(size_t)node * 128 + j0]) =
            make_float4(f0.x, f0.y, f1.x, f1.y);
        *reinterpret_cast<float4*>(&g_yp[(size_t)node * 128 + j0 + 4]) =
            make_float4(f2.x, f2.y, f3.x, f3.y);
    }
}

// ---------------- layer-0 mlp1 part B: += ea @ Wcat[64:96,:], epilogue ----------------
__global__ void k_mlp1b(const float* __restrict__ W1_rel,
                        const float* __restrict__ W1_root,
                        const float* __restrict__ b1_root) {
    extern __shared__ float sm[];
    float* xs = sm;            // [64][36]
    float* Ws = sm + 64 * 36;  // [32][128]
    float* b1 = Ws + 32 * 128; // [64]
    const int tid = threadIdx.x;
    const int node0 = blockIdx.x * 64;

    for (int i = tid; i < 32 * 128; i += 256) {
        int k = i >> 7, j = i & 127;
        Ws[i] = (j < 64) ? W1_rel[(64 + k) * 64 + j] : W1_root[(64 + k) * 64 + (j - 64)];
    }
    if (tid < 64) b1[tid] = b1_root[tid];
    for (int i = tid; i < 64 * 32; i += 256) {
        int n = i >> 5, k = i & 31;
        int node = node0 + n;
        xs[n * 36 + k] = (node < N_NODES) ? g_edge_aggr[(size_t)node * EC + k] : 0.f;
    }
    __syncthreads();

    const int og = tid & 15, ng = tid >> 4;
    const int j0 = og * 8;
    unsigned long long acc[4][4];
#pragma unroll
    for (int i = 0; i < 4; i++)
#pragma unroll
        for (int j = 0; j < 4; j++) acc[i][j] = 0ull;

#pragma unroll 4
    for (int k = 0; k < 32; k++) {
        ulonglong2 wA = *reinterpret_cast<const ulonglong2*>(&Ws[k * 128 + j0]);
        ulonglong2 wB = *reinterpret_cast<const ulonglong2*>(&Ws[k * 128 + j0 + 4]);
#pragma unroll
        for (int i = 0; i < 4; i++) {
            unsigned long long aa = bcast2(xs[(ng + 16 * i) * 36 + k]);
            ffma2(acc[i][0], aa, wA.x);
            ffma2(acc[i][1], aa, wA.y);
            ffma2(acc[i][2], aa, wB.x);
            ffma2(acc[i][3], aa, wB.y);
        }
    }

#pragma unroll
    for (int i = 0; i < 4; i++) {
        int node = node0 + ng + 16 * i;
        if (node >= N_NODES) continue;
        float4 p0 = *reinterpret_cast<const float4*>(&g_yp[(size_t)node * 128 + j0]);
        float4 p1 = *reinterpret_cast<const float4*>(&g_yp[(size_t)node * 128 + j0 + 4]);
        float2 f0 = u2f(acc[i][0]), f1 = u2f(acc[i][1]);
        float2 f2 = u2f(acc[i][2]), f3 = u2f(acc[i][3]);
        float v0 = p0.x + f0.x, v1 = p0.y + f0.y, v2 = p0.z + f1.x, v3 = p0.w + f1.y;
        float v4 = p1.x + f2.x, v5 = p1.y + f2.y, v6 = p1.z + f3.x, v7 = p1.w + f3.y;
        if (og < 8) {
            __half2 h0 = __floats2half2_rn(v0, v1);
            __half2 h1 = __floats2half2_rn(v2, v3);
            __half2 h2 = __floats2half2_rn(v4, v5);
            __half2 h3 = __floats2half2_rn(v6, v7);
            uint4 pk;
            pk.x = *reinterpret_cast<unsigned int*>(&h0);
            pk.y = *reinterpret_cast<unsigned int*>(&h1);
            pk.z = *reinterpret_cast<unsigned int*>(&h2);
            pk.w = *reinterpret_cast<unsigned int*>(&h3);
            *reinterpret_cast<uint4*>(&g_y[(size_t)node * 64 + j0]) = pk;
        } else {
            int jr = j0 - 64;
            float4 o0 = make_float4(fmaxf(v0 + b1[jr + 0], 0.f), fmaxf(v1 + b1[jr + 1], 0.f),
                                    fmaxf(v2 + b1[jr + 2], 0.f), fmaxf(v3 + b1[jr + 3], 0.f));
            float4 o1 = make_float4(fmaxf(v4 + b1[jr + 4], 0.f), fmaxf(v5 + b1[jr + 5], 0.f),
                                    fmaxf(v6 + b1[jr + 6], 0.f), fmaxf(v7 + b1[jr + 7], 0.f));
            *reinterpret_cast<float4*>(&g_u[(size_t)node * 64 + jr]) = o0;
            *reinterpret_cast<float4*>(&g_u[(size_t)node * 64 + jr + 4]) = o1;
        }
    }
}

// ---------------- fused node MLP stage 1 (layer 1) ----------------
__global__ void k_node_mlp1(const float* __restrict__ x_in,
                            const float* __restrict__ W1_rel,
                            const float* __restrict__ W1_root,
                            const float* __restrict__ b1_root) {
    extern __shared__ float sm[];
    float* xs = sm;            // [64][100]
    float* Ws = sm + 6400;     // [96][128]
    float* b1 = Ws + 12288;    // [64]
    const int tid = threadIdx.x;
    const int node0 = blockIdx.x * 64;

    for (int i = tid; i < 96 * 128; i += 256) {
        int k = i >> 7, j = i & 127;
        Ws[i] = (j < 64) ? W1_rel[k * 64 + j] : W1_root[k * 64 + (j - 64)];
    }
    if (tid < 64) b1[tid] = b1_root[tid];
    for (int i = tid; i < 64 * 96; i += 256) {
        int n = i / 96, k = i - n * 96;
        int node = node0 + n;
        float v = 0.f;
        if (node < N_NODES)
            v = (k < 64) ? x_in[(size_t)node * 64 + k]
                         : g_edge_aggr[(size_t)node * EC + (k - 64)];
        xs[n * 100 + k] = v;
    }
    __syncthreads();

    const int og = tid & 15, ng = tid >> 4;
    const int j0 = og * 8;
    unsigned long long acc[4][4];
#pragma unroll
    for (int i = 0; i < 4; i++)
#pragma unroll
        for (int j = 0; j < 4; j++) acc[i][j] = 0ull;

#pragma unroll 4
    for (int k = 0; k < 96; k++) {
        ulonglong2 wA = *reinterpret_cast<const ulonglong2*>(&Ws[k * 128 + j0]);
        ulonglong2 wB = *reinterpret_cast<const ulonglong2*>(&Ws[k * 128 + j0 + 4]);
#pragma unroll
        for (int i = 0; i < 4; i++) {
            unsigned long long aa = bcast2(xs[(ng + 16 * i) * 100 + k]);
            ffma2(acc[i][0], aa, wA.x);
            ffma2(acc[i][1], aa, wA.y);
            ffma2(acc[i][2], aa, wB.x);
            ffma2(acc[i][3], aa, wB.y);
        }
    }

#pragma unroll
    for (int i = 0; i < 4; i++) {
        int node = node0 + ng + 16 * i;
        if (node >= N_NODES) continue;
        float2 f0 = u2f(acc[i][0]), f1 = u2f(acc[i][1]);
        float2 f2 = u2f(acc[i][2]), f3 = u2f(acc[i][3]);
        if (og < 8) {
            __half2 h0 = __floats2half2_rn(f0.x, f0.y);
            __half2 h1 = __floats2half2_rn(f1.x, f1.y);
            __half2 h2 = __floats2half2_rn(f2.x, f2.y);
            __half2 h3 = __floats2half2_rn(f3.x, f3.y);
            uint4 pk;
            pk.x = *reinterpret_cast<unsigned int*>(&h0);
            pk.y = *reinterpret_cast<unsigned int*>(&h1);
            pk.z = *reinterpret_cast<unsigned int*>(&h2);
            pk.w = *reinterpret_cast<unsigned int*>(&h3);
            *reinterpret_cast<uint4*>(&g_y[(size_t)node * 64 + j0]) = pk;
        } else {
            int jr = j0 - 64;
            float4 o0 = make_float4(fmaxf(f0.x + b1[jr + 0], 0.f),
                                    fmaxf(f0.y + b1[jr + 1], 0.f),
                                    fmaxf(f1.x + b1[jr + 2], 0.f),
                                    fmaxf(f1.y + b1[jr + 3], 0.f));
            float4 o1 = make_float4(fmaxf(f2.x + b1[jr + 4], 0.f),
                                    fmaxf(f2.y + b1[jr + 5], 0.f),
                                    fmaxf(f3.x + b1[jr + 6], 0.f),
                                    fmaxf(f3.y + b1[jr + 7], 0.f));
            *reinterpret_cast<float4*>(&g_u[(size_t)node * 64 + jr]) = o0;
            *reinterpret_cast<float4*>(&g_u[(size_t)node * 64 + jr + 4]) = o1;
        }
    }
}

// ---------------- node MLP stage 2 + fused pooling on last layer ----------------
__global__ void k_node_mlp2(const float* __restrict__ b1_rel,
                            const float* __restrict__ W2_rel,
                            const float* __restrict__ W2_root,
                            const float* __restrict__ b2_rel,
                            const float* __restrict__ b2_root,
                            const int* __restrict__ batch,
                            int final_layer) {
    extern __shared__ float sm[];
    float* As = sm;            // [64][132]
    float* Ws = sm + 8448;     // [128][64]
    float* b2 = Ws + 8192;     // [64]
    const int tid = threadIdx.x;
    const int node0 = blockIdx.x * 64;

    for (int i = tid; i < 128 * 64; i += 256) {
        int k = i >> 6, j = i & 63;
        Ws[i] = (k < 64) ? W2_rel[k * 64 + j] : W2_root[(k - 64) * 64 + j];
    }
    if (tid < 64) b2[tid] = b2_rel[tid] + b2_root[tid];
    for (int i = tid; i < 64 * 128; i += 256) {
        int n = i >> 7, k = i & 127;
        int node = node0 + n;
        float v = 0.f;
        if (node < N_NODES) {
            if (k < 64) v = fmaxf(g_agg[(size_t)node * 64 + k] + b1_rel[k], 0.f);
            else        v = g_u[(size_t)node * 64 + (k - 64)];
        }
        As[n * 132 + k] = v;
    }
    __syncthreads();

    const int og = tid & 15, ng = tid >> 4;
    const int j0 = og * 4;
    unsigned long long acc[4][2];
#pragma unroll
    for (int i = 0; i < 4; i++) { acc[i][0] = 0ull; acc[i][1] = 0ull; }

#pragma unroll 4
    for (int k = 0; k < 128; k++) {
        ulonglong2 w = *reinterpret_cast<const ulonglong2*>(&Ws[k * 64 + j0]);
#pragma unroll
        for (int i = 0; i < 4; i++) {
            unsigned long long aa = bcast2(As[(ng + 16 * i) * 132 + k]);
            ffma2(acc[i][0], aa, w.x);
            ffma2(acc[i][1], aa, w.y);
        }
    }

#pragma unroll
    for (int i = 0; i < 4; i++) {
        int node = node0 + ng + 16 * i;
        if (node >= N_NODES) continue;
        float2 f0 = u2f(acc[i][0]), f1 = u2f(acc[i][1]);
        float4 o = make_float4(fmaxf(f0.x + b2[j0 + 0], 0.f),
                               fmaxf(f0.y + b2[j0 + 1], 0.f),
                               fmaxf(f1.x + b2[j0 + 2], 0.f),
                               fmaxf(f1.y + b2[j0 + 3], 0.f));
        if (final_layer) {
            int b = batch[node];
            red4(&g_pooled[(size_t)b * 64 + j0], o);
        } else {
            *reinterpret_cast<float4*>(&g_x[(size_t)node * 64 + j0]) = o;
        }
    }
}

// ---------------- final MLP ----------------
__global__ void k_final(const float* __restrict__ W1, const float* __restrict__ b1,
                        const float* __restrict__ W2, const float* __restrict__ b2,
                        float* __restrict__ out) {
    __shared__ float pr[64];
    __shared__ float h[64];
    int g = blockIdx.x;
    int j = threadIdx.x;
    pr[j] = g_pooled[g * 64 + j];
    __syncthreads();
    float s = b1[j];
#pragma unroll 8
    for (int k = 0; k < 64; k++) s = fmaf(pr[k], W1[k * 64 + j], s);
    h[j] = fmaxf(s, 0.f);
    __syncthreads();
    if (j < OUT_CH) {
        float s2 = b2[j];
#pragma unroll 8
        for (int k = 0; k < 64; k++) s2 = fmaf(h[k], W2[k * OUT_CH + j], s2);
        out[g * OUT_CH + j] = s2;
    }
}

// ---------------- launch ----------------
extern "C" void kernel_launch(void* const* d_in, const int* in_sizes, int n_in,
                              void* d_out, int out_size) {
    const float* x         = (const float*)d_in[0];
    const float* edge_attr = (const float*)d_in[1];
    const float* relW1[2]  = {(const float*)d_in[2],  (const float*)d_in[10]};
    const float* relb1[2]  = {(const float*)d_in[3],  (const float*)d_in[11]};
    const float* relW2[2]  = {(const float*)d_in[4],  (const float*)d_in[12]};
    const float* relb2[2]  = {(const float*)d_in[5],  (const float*)d_in[13]};
    const float* rootW1[2] = {(const float*)d_in[6],  (const float*)d_in[14]};
    const float* rootb1[2] = {(const float*)d_in[7],  (const float*)d_in[15]};
    const float* rootW2[2] = {(const float*)d_in[8],  (const float*)d_in[16]};
    const float* rootb2[2] = {(const float*)d_in[9],  (const float*)d_in[17]};
    const float* finW1 = (const float*)d_in[18];
    const float* finb1 = (const float*)d_in[19];
    const float* finW2 = (const float*)d_in[20];
    const float* finb2 = (const float*)d_in[21];
    const int* edge_index = (const int*)d_in[22];
    const int* batch      = (const int*)d_in[23];
    float* out = (float*)d_out;

    float *p_ea, *p_x, *p_pooled;
    int *p_icnt;
    cudaGetSymbolAddress((void**)&p_ea, g_edge_aggr);
    cudaGetSymbolAddress((void**)&p_x, g_x);
    cudaGetSymbolAddress((void**)&p_pooled, g_pooled);
    cudaGetSymbolAddress((void**)&p_icnt, g_icnt);

    const int SMEM1  = (6400 + 12288 + 64) * 4;          // 75008
    const int SMEM1A = (64 * 68 + 64 * 128) * 4;         // 50176
    const int SMEM1B = (64 * 36 + 32 * 128 + 64) * 4;    // 26112
    const int SMEM2  = (8448 + 8192 + 64) * 4;           // 66816
    cudaFuncSetAttribute(k_node_mlp1, cudaFuncAttributeMaxDynamicSharedMemorySize, SMEM1);
    cudaFuncSetAttribute(k_mlp1a, cudaFuncAttributeMaxDynamicSharedMemorySize, SMEM1A);
    cudaFuncSetAttribute(k_mlp1b, cudaFuncAttributeMaxDynamicSharedMemorySize, SMEM1B);
    cudaFuncSetAttribute(k_node_mlp2, cudaFuncAttributeMaxDynamicSharedMemorySize, SMEM2);

    static cudaStream_t s2 = nullptr;
    static cudaEvent_t evF = nullptr, evJ = nullptr;
    if (!s2) {
        cudaStreamCreateWithFlags(&s2, cudaStreamNonBlocking);
        cudaEventCreateWithFlags(&evF, cudaEventDisableTiming);
        cudaEventCreateWithFlags(&evJ, cudaEventDisableTiming);
    }

    const int NODE_BLOCKS = (N_NODES + 63) / 64;
    const int EDGE_BLOCKS = (N_EDGES + 255) / 256;
    const int GATHER_BLOCKS = (N_NODES * 32 + 255) / 256;

    // ---- fork: CSR build + x-part GEMM on side stream ----
    cudaEventRecord(evF, 0);
    cudaStreamWaitEvent(s2, evF, 0);
    cudaMemsetAsync(p_icnt, 0, 2 * N_NODES * sizeof(int), s2);
    k_hist<<<EDGE_BLOCKS, 256, 0, s2>>>(edge_index);
    k_scan<<<1, 1024, 0, s2>>>();
    k_fill<<<EDGE_BLOCKS, 256, 0, s2>>>(edge_index);
    k_mlp1a<<<NODE_BLOCKS, 256, SMEM1A, s2>>>(x, relW1[0], rootW1[0]);
    cudaEventRecord(evJ, s2);

    // ---- main stream ----
    cudaMemsetAsync(p_ea, 0, N_NODES * EC * sizeof(float), 0);
    cudaMemsetAsync(p_pooled, 0, G_GRAPHS * H_CH * sizeof(float), 0);
    k_edge_aggr<<<(N_EDGES / 4 * 8 + 255) / 256, 256>>>(edge_attr, edge_index, p_ea);

    cudaStreamWaitEvent(0, evJ, 0);
    k_mlp1b<<<NODE_BLOCKS, 256, SMEM1B>>>(relW1[0], rootW1[0], rootb1[0]);
    k_gather<<<GATHER_BLOCKS, 256>>>();
    k_node_mlp2<<<NODE_BLOCKS, 256, SMEM2>>>(relb1[0], relW2[0], rootW2[0],
                                             relb2[0], rootb2[0], batch, 0);

    k_node_mlp1<<<NODE_BLOCKS, 256, SMEM1>>>(p_x, relW1[1], rootW1[1], rootb1[1]);
    k_gather<<<GATHER_BLOCKS, 256>>>();
    k_node_mlp2<<<NODE_BLOCKS, 256, SMEM2>>>(relb1[1], relW2[1], rootW2[1],
                                             relb2[1], rootb2[1], batch, 1);

    k_final<<<G_GRAPHS, 64>>>(finW1, finb1, finW2, finb2, out);
}

// round 6
// speedup vs baseline: 1.0390x; 1.0390x over previous
#include <cuda_runtime.h>
#include <cuda_fp16.h>
#include <cstdint>

#define N_NODES 50000
#define N_EDGES 1600000
#define G_GRAPHS 256
#define IN_CH 64
#define EC 32
#define H_CH 64
#define OUT_CH 10

// ---------------- scratch ----------------
__device__ float  g_edge_aggr[N_NODES * EC];
__device__ __half g_y[N_NODES * H_CH];        // fp16 gather payload
__device__ float  g_u[N_NODES * H_CH];
__device__ float  g_agg[N_NODES * H_CH];
__device__ float  g_x[N_NODES * H_CH];
__device__ float  g_pooled[G_GRAPHS * H_CH];
__device__ int    g_icnt[2 * N_NODES];
__device__ int    g_off[N_NODES + 1];
__device__ int    g_csr[N_EDGES];

// ---------------- PTX helpers ----------------
__device__ __forceinline__ void red4(float* addr, float4 v) {
    asm volatile("red.global.add.v4.f32 [%0], {%1,%2,%3,%4};"
                 :: "l"(addr), "f"(v.x), "f"(v.y), "f"(v.z), "f"(v.w)
                 : "memory");
}
__device__ __forceinline__ void ffma2(unsigned long long& d,
                                      unsigned long long a, unsigned long long b) {
    asm("fma.rn.f32x2 %0, %1, %2, %0;" : "+l"(d) : "l"(a), "l"(b));
}
__device__ __forceinline__ unsigned long long bcast2(float a) {
    unsigned long long r;
    asm("mov.b64 %0, {%1, %1};" : "=l"(r) : "f"(a));
    return r;
}
__device__ __forceinline__ float2 u2f(unsigned long long v) {
    float2 f;
    asm("mov.b64 {%0, %1}, %2;" : "=f"(f.x), "=f"(f.y) : "l"(v));
    return f;
}

// ---------------- CSR build ----------------
__global__ void k_hist(const int* __restrict__ edge_index) {
    int e = blockIdx.x * blockDim.x + threadIdx.x;
    if (e >= N_EDGES) return;
    atomicAdd(&g_icnt[edge_index[N_EDGES + e]], 1);
}

__global__ void k_scan() {
    __shared__ int wsum[32];
    __shared__ int chunk_base;
    int tid = threadIdx.x, lane = tid & 31, wid = tid >> 5;
    if (tid == 0) chunk_base = 0;
    for (int start = 0; start < N_NODES; start += 4096) {
        __syncthreads();
        int idx = start + tid * 4;
        int a0 = 0, a1 = 0, a2 = 0, a3 = 0;
        if (idx + 3 < N_NODES) {
            int4 t = *reinterpret_cast<const int4*>(&g_icnt[idx]);
            a0 = t.x; a1 = t.y; a2 = t.z; a3 = t.w;
        } else if (idx < N_NODES) {
            a0 = g_icnt[idx];
            if (idx + 1 < N_NODES) a1 = g_icnt[idx + 1];
            if (idx + 2 < N_NODES) a2 = g_icnt[idx + 2];
        }
        int v = a0 + a1 + a2 + a3;
        int x = v;
#pragma unroll
        for (int d = 1; d < 32; d <<= 1) {
            int y = __shfl_up_sync(0xffffffffu, x, d);
            if (lane >= d) x += y;
        }
        if (lane == 31) wsum[wid] = x;
        __syncthreads();
        if (wid == 0) {
            int s = wsum[lane];
#pragma unroll
            for (int d = 1; d < 32; d <<= 1) {
                int y = __shfl_up_sync(0xffffffffu, s, d);
                if (lane >= d) s += y;
            }
            wsum[lane] = s;
        }
        __syncthreads();
        int wbase = (wid > 0) ? wsum[wid - 1] : 0;
        int base = chunk_base + wbase + x - v;
        if (idx < N_NODES)     g_off[idx]     = base;
        if (idx + 1 < N_NODES) g_off[idx + 1] = base + a0;
        if (idx + 2 < N_NODES) g_off[idx + 2] = base + a0 + a1;
        if (idx + 3 < N_NODES) g_off[idx + 3] = base + a0 + a1 + a2;
        __syncthreads();
        if (tid == 0) chunk_base += wsum[31];
    }
    __syncthreads();
    if (tid == 0) g_off[N_NODES] = chunk_base;
}

__global__ void k_fill(const int* __restrict__ edge_index) {
    int e = blockIdx.x * blockDim.x + threadIdx.x;
    if (e >= N_EDGES) return;
    int c = edge_index[N_EDGES + e];
    int pos = g_off[c] + atomicAdd(&g_icnt[N_NODES + c], 1);
    g_csr[pos] = edge_index[e];
}

// ---------------- edge_attr aggregation ----------------
__global__ void k_edge_aggr(const float* __restrict__ edge_attr,
                            const int* __restrict__ edge_index,
                            float* __restrict__ out) {
    const int Q = N_EDGES / 4;
    int tid = blockIdx.x * blockDim.x + threadIdx.x;
    int e = tid >> 3, p4 = (tid & 7) * 4;
    if (e >= Q) return;
    int e1 = e + Q, e2 = e + 2 * Q, e3 = e + 3 * Q;
    int r0 = edge_index[e],  r1 = edge_index[e1];
    int r2 = edge_index[e2], r3 = edge_index[e3];
    float4 v0 = *reinterpret_cast<const float4*>(edge_attr + (size_t)e  * EC + p4);
    float4 v1 = *reinterpret_cast<const float4*>(edge_attr + (size_t)e1 * EC + p4);
    float4 v2 = *reinterpret_cast<const float4*>(edge_attr + (size_t)e2 * EC + p4);
    float4 v3 = *reinterpret_cast<const float4*>(edge_attr + (size_t)e3 * EC + p4);
    red4(out + (size_t)r0 * EC + p4, v0);
    red4(out + (size_t)r1 * EC + p4, v1);
    red4(out + (size_t)r2 * EC + p4, v2);
    red4(out + (size_t)r3 * EC + p4, v3);
}

// ---------------- CSR gather: warp per node, divergence-free ----------------
__global__ void k_gather() {
    int node = (blockIdx.x * blockDim.x + threadIdx.x) >> 5;
    if (node >= N_NODES) return;
    int lane = threadIdx.x & 31;
    int g = lane >> 3;            // edge subgroup 0..3
    int p8 = (lane & 7) * 8;      // 8 halves = 16B column chunk
    int s = g_off[node], e = g_off[node + 1];

    float a0[8], a1[8];
#pragma unroll
    for (int q = 0; q < 8; q++) { a0[q] = 0.f; a1[q] = 0.f; }

    int i = s + g;
    for (; i + 4 < e; i += 8) {
        int n0 = g_csr[i], n1 = g_csr[i + 4];
        uint4 v0 = *reinterpret_cast<const uint4*>(&g_y[(size_t)n0 * H_CH + p8]);
        uint4 v1 = *reinterpret_cast<const uint4*>(&g_y[(size_t)n1 * H_CH + p8]);
        const __half2* h0 = reinterpret_cast<const __half2*>(&v0);
        const __half2* h1 = reinterpret_cast<const __half2*>(&v1);
#pragma unroll
        for (int q = 0; q < 4; q++) {
            float2 f0 = __half22float2(h0[q]);
            float2 f1 = __half22float2(h1[q]);
            a0[q * 2]     += f0.x;  a0[q * 2 + 1] += f0.y;
            a1[q * 2]     += f1.x;  a1[q * 2 + 1] += f1.y;
        }
    }
    if (i < e) {
        int n0 = g_csr[i];
        uint4 v0 = *reinterpret_cast<const uint4*>(&g_y[(size_t)n0 * H_CH + p8]);
        const __half2* h0 = reinterpret_cast<const __half2*>(&v0);
#pragma unroll
        for (int q = 0; q < 4; q++) {
            float2 f0 = __half22float2(h0[q]);
            a0[q * 2]     += f0.x;  a0[q * 2 + 1] += f0.y;
        }
    }

    float r[8];
#pragma unroll
    for (int q = 0; q < 8; q++) {
        r[q] = a0[q] + a1[q];
        r[q] += __shfl_xor_sync(0xffffffffu, r[q], 8);
        r[q] += __shfl_xor_sync(0xffffffffu, r[q], 16);
    }
    if (g == 0) {
        float4 o0 = make_float4(r[0], r[1], r[2], r[3]);
        float4 o1 = make_float4(r[4], r[5], r[6], r[7]);
        *reinterpret_cast<float4*>(&g_agg[(size_t)node * H_CH + p8])     = o0;
        *reinterpret_cast<float4*>(&g_agg[(size_t)node * H_CH + p8 + 4]) = o1;
    }
}

// ---------------- node MLP stage 1: 128 nodes / 512 threads ----------------
// y = xc @ W1_rel (fp16 out);  u = relu(xc @ W1_root + b1_root)
__global__ void __launch_bounds__(512, 2)
k_node_mlp1(const float* __restrict__ x_in,
            const float* __restrict__ W1_rel,
            const float* __restrict__ W1_root,
            const float* __restrict__ b1_root) {
    extern __shared__ float sm[];
    float* xs = sm;                // [128][100]
    float* Ws = sm + 128 * 100;    // [96][128]
    float* b1 = Ws + 96 * 128;     // [64]
    const int tid = threadIdx.x;
    const int node0 = blockIdx.x * 128;

    for (int i = tid; i < 96 * 128; i += 512) {
        int k = i >> 7, j = i & 127;
        Ws[i] = (j < 64) ? W1_rel[k * 64 + j] : W1_root[k * 64 + (j - 64)];
    }
    if (tid < 64) b1[tid] = b1_root[tid];
    for (int i = tid; i < 128 * 96; i += 512) {
        int n = i / 96, k = i - n * 96;
        int node = node0 + n;
        float v = 0.f;
        if (node < N_NODES)
            v = (k < 64) ? x_in[(size_t)node * 64 + k]
                         : g_edge_aggr[(size_t)node * EC + (k - 64)];
        xs[n * 100 + k] = v;
    }
    __syncthreads();

    const int og = tid & 15, ng = tid >> 4;   // ng: 0..31
    const int j0 = og * 8;
    unsigned long long acc[4][4];
#pragma unroll
    for (int i = 0; i < 4; i++)
#pragma unroll
        for (int j = 0; j < 4; j++) acc[i][j] = 0ull;

#pragma unroll 4
    for (int k = 0; k < 96; k++) {
        ulonglong2 wA = *reinterpret_cast<const ulonglong2*>(&Ws[k * 128 + j0]);
        ulonglong2 wB = *reinterpret_cast<const ulonglong2*>(&Ws[k * 128 + j0 + 4]);
#pragma unroll
        for (int i = 0; i < 4; i++) {
            unsigned long long aa = bcast2(xs[(ng + 32 * i) * 100 + k]);
            ffma2(acc[i][0], aa, wA.x);
            ffma2(acc[i][1], aa, wA.y);
            ffma2(acc[i][2], aa, wB.x);
            ffma2(acc[i][3], aa, wB.y);
        }
    }

#pragma unroll
    for (int i = 0; i < 4; i++) {
        int node = node0 + ng + 32 * i;
        if (node >= N_NODES) continue;
        float2 f0 = u2f(acc[i][0]), f1 = u2f(acc[i][1]);
        float2 f2 = u2f(acc[i][2]), f3 = u2f(acc[i][3]);
        if (og < 8) {
            __half2 h0 = __floats2half2_rn(f0.x, f0.y);
            __half2 h1 = __floats2half2_rn(f1.x, f1.y);
            __half2 h2 = __floats2half2_rn(f2.x, f2.y);
            __half2 h3 = __floats2half2_rn(f3.x, f3.y);
            uint4 pk;
            pk.x = *reinterpret_cast<unsigned int*>(&h0);
            pk.y = *reinterpret_cast<unsigned int*>(&h1);
            pk.z = *reinterpret_cast<unsigned int*>(&h2);
            pk.w = *reinterpret_cast<unsigned int*>(&h3);
            *reinterpret_cast<uint4*>(&g_y[(size_t)node * 64 + j0]) = pk;
        } else {
            int jr = j0 - 64;
            float4 o0 = make_float4(fmaxf(f0.x + b1[jr + 0], 0.f),
                                    fmaxf(f0.y + b1[jr + 1], 0.f),
                                    fmaxf(f1.x + b1[jr + 2], 0.f),
                                    fmaxf(f1.y + b1[jr + 3], 0.f));
            float4 o1 = make_float4(fmaxf(f2.x + b1[jr + 4], 0.f),
                                    fmaxf(f2.y + b1[jr + 5], 0.f),
                                    fmaxf(f3.x + b1[jr + 6], 0.f),
                                    fmaxf(f3.y + b1[jr + 7], 0.f));
            *reinterpret_cast<float4*>(&g_u[(size_t)node * 64 + jr]) = o0;
            *reinterpret_cast<float4*>(&g_u[(size_t)node * 64 + jr + 4]) = o1;
        }
    }
}

// ---------------- node MLP stage 2: 128 nodes / 512 threads + fused pooling ----------------
__global__ void __launch_bounds__(512, 2)
k_node_mlp2(const float* __restrict__ b1_rel,
            const float* __restrict__ W2_rel,
            const float* __restrict__ W2_root,
            const float* __restrict__ b2_rel,
            const float* __restrict__ b2_root,
            const int* __restrict__ batch,
            int final_layer) {
    extern __shared__ float sm[];
    float* As = sm;                // [128][132]
    float* Ws = sm + 128 * 132;    // [128][64]
    float* b2 = Ws + 128 * 64;     // [64]
    const int tid = threadIdx.x;
    const int node0 = blockIdx.x * 128;

    for (int i = tid; i < 128 * 64; i += 512) {
        int k = i >> 6, j = i & 63;
        Ws[i] = (k < 64) ? W2_rel[k * 64 + j] : W2_root[(k - 64) * 64 + j];
    }
    if (tid < 64) b2[tid] = b2_rel[tid] + b2_root[tid];
    for (int i = tid; i < 128 * 128; i += 512) {
        int n = i >> 7, k = i & 127;
        int node = node0 + n;
        float v = 0.f;
        if (node < N_NODES) {
            if (k < 64) v = fmaxf(g_agg[(size_t)node * 64 + k] + b1_rel[k], 0.f);
            else        v = g_u[(size_t)node * 64 + (k - 64)];
        }
        As[n * 132 + k] = v;
    }
    __syncthreads();

    const int og = tid & 15, ng = tid >> 4;   // ng: 0..31
    const int j0 = og * 4;
    unsigned long long acc[4][2];
#pragma unroll
    for (int i = 0; i < 4; i++) { acc[i][0] = 0ull; acc[i][1] = 0ull; }

#pragma unroll 4
    for (int k = 0; k < 128; k++) {
        ulonglong2 w = *reinterpret_cast<const ulonglong2*>(&Ws[k * 64 + j0]);
#pragma unroll
        for (int i = 0; i < 4; i++) {
            unsigned long long aa = bcast2(As[(ng + 32 * i) * 132 + k]);
            ffma2(acc[i][0], aa, w.x);
            ffma2(acc[i][1], aa, w.y);
        }
    }

#pragma unroll
    for (int i = 0; i < 4; i++) {
        int node = node0 + ng + 32 * i;
        if (node >= N_NODES) continue;
        float2 f0 = u2f(acc[i][0]), f1 = u2f(acc[i][1]);
        float4 o = make_float4(fmaxf(f0.x + b2[j0 + 0], 0.f),
                               fmaxf(f0.y + b2[j0 + 1], 0.f),
                               fmaxf(f1.x + b2[j0 + 2], 0.f),
                               fmaxf(f1.y + b2[j0 + 3], 0.f));
        if (final_layer) {
            int b = batch[node];
            red4(&g_pooled[(size_t)b * 64 + j0], o);
        } else {
            *reinterpret_cast<float4*>(&g_x[(size_t)node * 64 + j0]) = o;
        }
    }
}

// ---------------- final MLP ----------------
__global__ void k_final(const float* __restrict__ W1, const float* __restrict__ b1,
                        const float* __restrict__ W2, const float* __restrict__ b2,
                        float* __restrict__ out) {
    __shared__ float pr[64];
    __shared__ float h[64];
    int g = blockIdx.x;
    int j = threadIdx.x;
    pr[j] = g_pooled[g * 64 + j];
    __syncthreads();
    float s = b1[j];
#pragma unroll 8
    for (int k = 0; k < 64; k++) s = fmaf(pr[k], W1[k * 64 + j], s);
    h[j] = fmaxf(s, 0.f);
    __syncthreads();
    if (j < OUT_CH) {
        float s2 = b2[j];
#pragma unroll 8
        for (int k = 0; k < 64; k++) s2 = fmaf(h[k], W2[k * OUT_CH + j], s2);
        out[g * OUT_CH + j] = s2;
    }
}

// ---------------- launch ----------------
extern "C" void kernel_launch(void* const* d_in, const int* in_sizes, int n_in,
                              void* d_out, int out_size) {
    const float* x         = (const float*)d_in[0];
    const float* edge_attr = (const float*)d_in[1];
    const float* relW1[2]  = {(const float*)d_in[2],  (const float*)d_in[10]};
    const float* relb1[2]  = {(const float*)d_in[3],  (const float*)d_in[11]};
    const float* relW2[2]  = {(const float*)d_in[4],  (const float*)d_in[12]};
    const float* relb2[2]  = {(const float*)d_in[5],  (const float*)d_in[13]};
    const float* rootW1[2] = {(const float*)d_in[6],  (const float*)d_in[14]};
    const float* rootb1[2] = {(const float*)d_in[7],  (const float*)d_in[15]};
    const float* rootW2[2] = {(const float*)d_in[8],  (const float*)d_in[16]};
    const float* rootb2[2] = {(const float*)d_in[9],  (const float*)d_in[17]};
    const float* finW1 = (const float*)d_in[18];
    const float* finb1 = (const float*)d_in[19];
    const float* finW2 = (const float*)d_in[20];
    const float* finb2 = (const float*)d_in[21];
    const int* edge_index = (const int*)d_in[22];
    const int* batch      = (const int*)d_in[23];
    float* out = (float*)d_out;

    float *p_ea, *p_x, *p_pooled;
    int *p_icnt;
    cudaGetSymbolAddress((void**)&p_ea, g_edge_aggr);
    cudaGetSymbolAddress((void**)&p_x, g_x);
    cudaGetSymbolAddress((void**)&p_pooled, g_pooled);
    cudaGetSymbolAddress((void**)&p_icnt, g_icnt);

    const int SMEM1 = (128 * 100 + 96 * 128 + 64) * 4;   // 100608 B
    const int SMEM2 = (128 * 132 + 128 * 64 + 64) * 4;   // 100608 B
    cudaFuncSetAttribute(k_node_mlp1, cudaFuncAttributeMaxDynamicSharedMemorySize, SMEM1);
    cudaFuncSetAttribute(k_node_mlp2, cudaFuncAttributeMaxDynamicSharedMemorySize, SMEM2);

    static cudaStream_t s2 = nullptr;
    static cudaEvent_t evF = nullptr, evJ = nullptr;
    if (!s2) {
        cudaStreamCreateWithFlags(&s2, cudaStreamNonBlocking);
        cudaEventCreateWithFlags(&evF, cudaEventDisableTiming);
        cudaEventCreateWithFlags(&evJ, cudaEventDisableTiming);
    }

    const int NODE_BLOCKS = (N_NODES + 127) / 128;   // 391
    const int EDGE_BLOCKS = (N_EDGES + 255) / 256;
    const int GATHER_BLOCKS = (N_NODES * 32 + 255) / 256;

    // ---- fork: CSR build on side stream ----
    cudaEventRecord(evF, 0);
    cudaStreamWaitEvent(s2, evF, 0);
    cudaMemsetAsync(p_icnt, 0, 2 * N_NODES * sizeof(int), s2);
    k_hist<<<EDGE_BLOCKS, 256, 0, s2>>>(edge_index);
    k_scan<<<1, 1024, 0, s2>>>();
    k_fill<<<EDGE_BLOCKS, 256, 0, s2>>>(edge_index);
    cudaEventRecord(evJ, s2);

    // ---- main stream ----
    cudaMemsetAsync(p_ea, 0, N_NODES * EC * sizeof(float), 0);
    cudaMemsetAsync(p_pooled, 0, G_GRAPHS * H_CH * sizeof(float), 0);
    k_edge_aggr<<<(N_EDGES / 4 * 8 + 255) / 256, 256>>>(edge_attr, edge_index, p_ea);

    k_node_mlp1<<<NODE_BLOCKS, 512, SMEM1>>>(x, relW1[0], rootW1[0], rootb1[0]);
    cudaStreamWaitEvent(0, evJ, 0);
    k_gather<<<GATHER_BLOCKS, 256>>>();
    k_node_mlp2<<<NODE_BLOCKS, 512, SMEM2>>>(relb1[0], relW2[0], rootW2[0],
                                             relb2[0], rootb2[0], batch, 0);

    k_node_mlp1<<<NODE_BLOCKS, 512, SMEM1>>>(p_x, relW1[1], rootW1[1], rootb1[1]);
    k_gather<<<GATHER_BLOCKS, 256>>>();
    k_node_mlp2<<<NODE_BLOCKS, 512, SMEM2>>>(relb1[1], relW2[1], rootW2[1],
                                             relb2[1], rootb2[1], batch, 1);

    k_final<<<G_GRAPHS, 64>>>(finW1, finb1, finW2, finb2, out);
}